// round 13
// baseline (speedup 1.0000x reference)
#include <cuda_runtime.h>
#include <cuda_bf16.h>

// Problem constants: B=4, L=1024, E=256, S=32, W=2S+1=65
#define BB 4
#define LL 1024
#define EE 256
#define LOG2E 1.4426950408889634f
#define PITCH2 130   // K/V transposed pitch (floats)
#define PPITCH 65    // pos_bias pair-table pitch (ull pairs per channel)

typedef unsigned long long ull;

// Device-global scratch (no allocations allowed)
__device__ float g_Q[BB * LL * EE];
__device__ float g_K[BB * LL * EE];
__device__ float g_V[BB * LL * EE];

// ---------------------------------------------------------------------------
// helpers
// ---------------------------------------------------------------------------
__device__ __forceinline__ float ex2f(float x) {
    float r; asm("ex2.approx.f32 %0, %1;" : "=f"(r) : "f"(x)); return r;
}
__device__ __forceinline__ float rcpf(float x) {
    float r; asm("rcp.approx.f32 %0, %1;" : "=f"(r) : "f"(x)); return r;
}
__device__ __forceinline__ ull pack2s(float x) {
    ull r; unsigned u = __float_as_uint(x);
    asm("mov.b64 %0, {%1, %1};" : "=l"(r) : "r"(u)); return r;
}
__device__ __forceinline__ ull add2(ull a, ull b) {
    ull r; asm("add.rn.f32x2 %0, %1, %2;" : "=l"(r) : "l"(a), "l"(b)); return r;
}
__device__ __forceinline__ ull mul2(ull a, ull b) {
    ull r; asm("mul.rn.f32x2 %0, %1, %2;" : "=l"(r) : "l"(a), "l"(b)); return r;
}
__device__ __forceinline__ ull fma2v(ull a, ull b, ull c) {
    ull r; asm("fma.rn.f32x2 %0, %1, %2, %3;" : "=l"(r) : "l"(a), "l"(b), "l"(c)); return r;
}
__device__ __forceinline__ void unpk2(float& lo, float& hi, ull v) {
    unsigned a, b;
    asm("mov.b64 {%0, %1}, %2;" : "=r"(a), "=r"(b) : "l"(v));
    lo = __uint_as_float(a); hi = __uint_as_float(b);
}
__device__ __forceinline__ float inbf(int j) {
    return ((unsigned)j < (unsigned)LL) ? 1.0f : 0.0f;
}
// Packed exp2 for two lanes via FMA-pipe polynomial (no MUFU).
// l2 = packed log2-domain logits (|l| < ~60 on this data); rel err ~6e-5.
__device__ __forceinline__ void pexp2(ull l2, ull MAG, ull NEG1,
                                      ull C4, ull C3, ull C2, ull C1, ull ONE,
                                      float& p0, float& p1) {
    const ull r2  = add2(l2, MAG);            // rint(l) in mantissa (RN)
    const ull nn2 = fma2v(r2, NEG1, MAG);     // -n = MAG - r
    const ull f2  = add2(l2, nn2);            // f = l - n, f in [-0.5, 0.5]
    ull p2 = fma2v(f2, C4, C3);
    p2 = fma2v(f2, p2, C2);
    p2 = fma2v(f2, p2, C1);
    p2 = fma2v(f2, p2, ONE);                  // 2^f (Taylor deg-4)
    float rx, ry, px, py;
    unpk2(rx, ry, r2);
    unpk2(px, py, p2);
    // splice exponent: bits(r) = 0x4B400000 + n, low 9 bits of 0x4B400000 = 0
    p0 = __int_as_float((int)(__float_as_int(px) + ((unsigned)__float_as_int(rx) << 23)));
    p1 = __int_as_float((int)(__float_as_int(py) + ((unsigned)__float_as_int(ry) << 23)));
}
__device__ __forceinline__ void ldsm4(unsigned* r, unsigned addr) {
    asm volatile("ldmatrix.sync.aligned.m8n8.x4.shared.b16 {%0,%1,%2,%3}, [%4];"
                 : "=r"(r[0]), "=r"(r[1]), "=r"(r[2]), "=r"(r[3]) : "r"(addr));
}
__device__ __forceinline__ void mma16816(float* c, const unsigned* a, const unsigned* b) {
    asm volatile(
        "mma.sync.aligned.m16n8k16.row.col.f32.bf16.bf16.f32 "
        "{%0,%1,%2,%3},{%4,%5,%6,%7},{%8,%9},{%0,%1,%2,%3};"
        : "+f"(c[0]), "+f"(c[1]), "+f"(c[2]), "+f"(c[3])
        : "r"(a[0]), "r"(a[1]), "r"(a[2]), "r"(a[3]), "r"(b[0]), "r"(b[1]));
}

// Convert 8 fp32 -> 8 bf16 hi + 8 bf16 lo (residual); store as uint4 pairs.
__device__ __forceinline__ void cvt8store(__nv_bfloat16* dh, __nv_bfloat16* dl,
                                          float4 a, float4 b) {
    float v[8] = {a.x, a.y, a.z, a.w, b.x, b.y, b.z, b.w};
    __nv_bfloat16 h[8], l[8];
    #pragma unroll
    for (int j = 0; j < 8; ++j) {
        h[j] = __float2bfloat16(v[j]);
        l[j] = __float2bfloat16(v[j] - __bfloat162float(h[j]));
    }
    *(uint4*)dh = *(uint4*)h;
    *(uint4*)dl = *(uint4*)l;
}

// ---------------------------------------------------------------------------
// Kernel 1: QKV projection via tensor cores (FROZEN — measured ~10.4us).
// ---------------------------------------------------------------------------
__global__ __launch_bounds__(256, 2) void qkv_mma(
    const float* __restrict__ A,
    const float* __restrict__ W0, const float* __restrict__ W1,
    const float* __restrict__ W2,
    const float* __restrict__ bq, const float* __restrict__ bk,
    const float* __restrict__ bv)
{
    __shared__ __align__(16) __nv_bfloat16 sA[2][128 * 40];
    __shared__ __align__(16) __nv_bfloat16 sW[2][64 * 40];

    const int tid = threadIdx.x;
    const int z  = blockIdx.z;
    const int m0 = blockIdx.x * 128;
    const int n0 = blockIdx.y * 64;
    const float* Wm = (z == 0) ? W0 : (z == 1) ? W1 : W2;

    const int lane = tid & 31, wid = tid >> 5;
    const int wm = wid & 3;
    const int wn = wid >> 2;
    const int lr  = tid >> 2;
    const int lkf = (tid & 3) * 8;

    float acc[2][4][4];
    #pragma unroll
    for (int mt = 0; mt < 2; ++mt)
        #pragma unroll
        for (int nt = 0; nt < 4; ++nt)
            #pragma unroll
            for (int r = 0; r < 4; ++r) acc[mt][nt][r] = 0.0f;

    const int mat = lane >> 3;
    const int a_m = (mat & 1) * 8 + (lane & 7);
    const int a_k = (mat >> 1) * 8;
    const int w_n = (mat >> 1) * 8 + (lane & 7);
    const int w_k = (mat & 1) * 8;

    float4 pa0a, pa0b, pa1a, pa1b, pw0a, pw0b;
    {
        const float* pA0 = &A [(m0 +      lr) * EE + lkf];
        const float* pA1 = &A [(m0 + 64 + lr) * EE + lkf];
        const float* pW  = &Wm[(n0 +      lr) * EE + lkf];
        pa0a = *(const float4*)(pA0);     pa0b = *(const float4*)(pA0 + 4);
        pa1a = *(const float4*)(pA1);     pa1b = *(const float4*)(pA1 + 4);
        pw0a = *(const float4*)(pW);      pw0b = *(const float4*)(pW + 4);
    }

    for (int kt = 0; kt < 8; ++kt) {
        __syncthreads();
        cvt8store(&sA[0][lr * 40 + lkf],        &sA[1][lr * 40 + lkf],        pa0a, pa0b);
        cvt8store(&sA[0][(64 + lr) * 40 + lkf], &sA[1][(64 + lr) * 40 + lkf], pa1a, pa1b);
        cvt8store(&sW[0][lr * 40 + lkf],        &sW[1][lr * 40 + lkf],        pw0a, pw0b);
        __syncthreads();

        if (kt < 7) {
            const int k0 = (kt + 1) * 32;
            const float* pA0 = &A [(m0 +      lr) * EE + k0 + lkf];
            const float* pA1 = &A [(m0 + 64 + lr) * EE + k0 + lkf];
            const float* pW  = &Wm[(n0 +      lr) * EE + k0 + lkf];
            pa0a = *(const float4*)(pA0);     pa0b = *(const float4*)(pA0 + 4);
            pa1a = *(const float4*)(pA1);     pa1b = *(const float4*)(pA1 + 4);
            pw0a = *(const float4*)(pW);      pw0b = *(const float4*)(pW + 4);
        }

        #pragma unroll
        for (int ks = 0; ks < 2; ++ks) {
            unsigned ah[2][4], al[2][4], bh[4][2], bl[4][2];
            #pragma unroll
            for (int mt = 0; mt < 2; ++mt) {
                unsigned adr_h = (unsigned)__cvta_generic_to_shared(
                    &sA[0][(wm * 32 + mt * 16 + a_m) * 40 + ks * 16 + a_k]);
                unsigned adr_l = (unsigned)__cvta_generic_to_shared(
                    &sA[1][(wm * 32 + mt * 16 + a_m) * 40 + ks * 16 + a_k]);
                ldsm4(ah[mt], adr_h);
                ldsm4(al[mt], adr_l);
            }
            #pragma unroll
            for (int np = 0; np < 2; ++np) {
                unsigned t[4];
                unsigned adr_h = (unsigned)__cvta_generic_to_shared(
                    &sW[0][(wn * 32 + np * 16 + w_n) * 40 + ks * 16 + w_k]);
                ldsm4(t, adr_h);
                bh[np * 2][0] = t[0]; bh[np * 2][1] = t[1];
                bh[np * 2 + 1][0] = t[2]; bh[np * 2 + 1][1] = t[3];
                unsigned adr_l = (unsigned)__cvta_generic_to_shared(
                    &sW[1][(wn * 32 + np * 16 + w_n) * 40 + ks * 16 + w_k]);
                ldsm4(t, adr_l);
                bl[np * 2][0] = t[0]; bl[np * 2][1] = t[1];
                bl[np * 2 + 1][0] = t[2]; bl[np * 2 + 1][1] = t[3];
            }
            #pragma unroll
            for (int mt = 0; mt < 2; ++mt)
                #pragma unroll
                for (int nt = 0; nt < 4; ++nt) {
                    mma16816(acc[mt][nt], ah[mt], bh[nt]);
                    mma16816(acc[mt][nt], ah[mt], bl[nt]);
                    mma16816(acc[mt][nt], al[mt], bh[nt]);
                }
        }
    }

    float* out = (z == 0) ? g_Q : (z == 1) ? g_K : g_V;
    const float* bias = (z == 0) ? bq : (z == 1) ? bk : bv;
    #pragma unroll
    for (int nt = 0; nt < 4; ++nt) {
        const int n = n0 + wn * 32 + nt * 8 + (lane & 3) * 2;
        const float b0 = bias[n], b1 = bias[n + 1];
        #pragma unroll
        for (int mt = 0; mt < 2; ++mt) {
            const int m = m0 + wm * 32 + mt * 16 + (lane >> 2);
            float2 r0 = make_float2(acc[mt][nt][0] + b0, acc[mt][nt][1] + b1);
            float2 r1 = make_float2(acc[mt][nt][2] + b0, acc[mt][nt][3] + b1);
            *(float2*)&out[m * EE + n] = r0;
            *(float2*)&out[(m + 8) * EE + n] = r1;
        }
    }
}

// ---------------------------------------------------------------------------
// Kernel 2: AFT-local attention — MUFU/FMA hybrid exp.
// 2-row pairing (il, il+2): row A's exps on MUFU (ex2), row C's on the
// FMA-pipe packed poly (pexp2) — halves MUFU pressure (the measured floor).
// Packed f32x2 logits for both rows; pos_bias PAIRS pre-packed in smem
// (ull table, pitch 65 -> aligned LDS.64). Window coverage identical to the
// verified round-12 kernel. Unshifted softmax (logits bounded, no overflow).
// ---------------------------------------------------------------------------
template <int PAR, bool CHECK>
__device__ __forceinline__ void pair2h(
    const int il, const int j0, const int gq0,
    const float* __restrict__ Kc, const float* __restrict__ Vc,
    const ull* __restrict__ Pp,                 // pair table for this channel
    float* __restrict__ out)
{
    // packed constants (materialized per call; ptxas may rematerialize)
    const ull MAG  = pack2s(12582912.0f);       // 1.5 * 2^23
    const ull NEG1 = pack2s(-1.0f);
    const ull C4   = pack2s(0.00961813f);       // ln2^4/24
    const ull C3   = pack2s(0.05550411f);       // ln2^3/6
    const ull C2   = pack2s(0.24022651f);       // ln2^2/2
    const ull C1   = pack2s(0.69314718f);       // ln2
    const ull ONE  = pack2s(1.0f);
    const float2* Ppf = (const float2*)Pp;

    const int A = il, C = il + 2;
    const float qA = g_Q[gq0 + A * EE] * LOG2E;
    const float qC = g_Q[gq0 + C * EE] * LOG2E;
    const ull qA2 = pack2s(qA), qC2 = pack2s(qC);

    // boundary windows w=0 / w=64: K masked to 0 -> p = valid ? 1 : 0
    float denA, numA, denC, numC;
    {
        float vA0 = 1.f, vA6 = 1.f, vC0 = 1.f, vC6 = 1.f;
        if (CHECK) {
            vA0 = inbf(j0 + A); vA6 = inbf(j0 + A + 64);
            vC0 = inbf(j0 + C); vC6 = inbf(j0 + C + 64);
        }
        denA = vA0 + vA6;  numA = Vc[A] + Vc[A + 64];
        denC = vC0 + vC6;  numC = Vc[C] + Vc[C + 64];
    }

    const float px1  = Ppf[1].x;                // pb[1]
    const float px63 = Ppf[63].x;               // pb[63]

    if (PAR == 0) {   // A's w=1 at r=il+1 (not covered by even-aligned pairs)
        float p = ex2f(qA * (Kc[il + 1] + px1));
        if (CHECK) p *= inbf(j0 + il + 1);
        denA += p; numA = fmaf(p, Vc[il + 1], numA);
    }

    const int rbase = il + 2 - PAR;             // even

    // ---- t = 0 peeled: A full pair (scalar MUFU); C edge ----
    {
        const float2 pbt0 = Ppf[2 - PAR];       // {pb[2-PAR], pb[3-PAR]}
        const float2 k2 = *(const float2*)&Kc[rbase];
        const float2 v2 = *(const float2*)&Vc[rbase];
        float m0 = 1.f, m1 = 1.f;
        if (CHECK) { m0 = inbf(j0 + rbase); m1 = inbf(j0 + rbase + 1); }
        float p0 = ex2f(qA * (k2.x + pbt0.x));
        float p1 = ex2f(qA * (k2.y + pbt0.y));
        if (CHECK) { p0 *= m0; p1 *= m1; }
        denA += p0 + p1;
        numA = fmaf(p0, v2.x, numA);
        numA = fmaf(p1, v2.y, numA);
        if (PAR == 0) {   // C's w'=1 on lane1 (r = rbase+1 = il+3)
            float p = ex2f(qC * (k2.y + px1));
            if (CHECK) p *= m1;
            denC += p; numC = fmaf(p, v2.y, numC);
        }
    }

    // ---- middle t = 1..30: packed logits; A via MUFU, C via FMA-poly ----
    ull pbA2 = Pp[4 - PAR];
    ull pbC2 = Pp[2 - PAR];
    #pragma unroll 6
    for (int t = 1; t <= 30; ++t) {
        const int r = rbase + 2 * t;
        const ull    k2u = *(const ull*)&Kc[r];     // LDS.64
        const float2 v2  = *(const float2*)&Vc[r];
        const ull lA2 = mul2(add2(k2u, pbA2), qA2);
        const ull lC2 = mul2(add2(k2u, pbC2), qC2);
        float la0, la1; unpk2(la0, la1, lA2);
        float pa0 = ex2f(la0), pa1 = ex2f(la1);     // MUFU
        float pc0, pc1;
        pexp2(lC2, MAG, NEG1, C4, C3, C2, C1, ONE, pc0, pc1);   // FMA pipe
        if (CHECK) {
            const float m0 = inbf(j0 + r), m1 = inbf(j0 + r + 1);
            pa0 *= m0; pa1 *= m1; pc0 *= m0; pc1 *= m1;
        }
        denA += pa0 + pa1;
        denC += pc0 + pc1;
        numA = fmaf(pa0, v2.x, numA);  numA = fmaf(pa1, v2.y, numA);
        numC = fmaf(pc0, v2.x, numC);  numC = fmaf(pc1, v2.y, numC);
        pbC2 = pbA2;
        pbA2 = Pp[2 - PAR + 2 * t + 2];   // t=30 reads Pp[64-PAR]: in-bounds, unused for PAR=0
    }

    float pC0, pC1; unpk2(pC0, pC1, pbC2);          // carried C pair (scalars)

    // ---- tail (scalar MUFU; counts negligible) ----
    if (PAR == 0) {
        // t=31: A none (w=64 boundary); C full pair (62,63) via carried pC
        const int r = rbase + 62;                   // il + 64
        const float2 k2 = *(const float2*)&Kc[r];
        const float2 v2 = *(const float2*)&Vc[r];
        float m0 = 1.f, m1 = 1.f;
        if (CHECK) { m0 = inbf(j0 + r); m1 = inbf(j0 + r + 1); }
        float pc0 = ex2f(qC * (k2.x + pC0));
        float pc1 = ex2f(qC * (k2.y + pC1));
        if (CHECK) { pc0 *= m0; pc1 *= m1; }
        denC += pc0 + pc1;
        numC = fmaf(pc0, v2.x, numC);
        numC = fmaf(pc1, v2.y, numC);
    } else {
        // t=31: A single w=63 (lane0); C full pair (61,62) via carried pC
        const int r = rbase + 62;                   // il + 63
        const float2 k2 = *(const float2*)&Kc[r];
        const float2 v2 = *(const float2*)&Vc[r];
        float m0 = 1.f, m1 = 1.f;
        if (CHECK) { m0 = inbf(j0 + r); m1 = inbf(j0 + r + 1); }
        float pa = ex2f(qA * (k2.x + px63));
        if (CHECK) pa *= m0;
        denA += pa; numA = fmaf(pa, v2.x, numA);
        float pc0 = ex2f(qC * (k2.x + pC0));
        float pc1 = ex2f(qC * (k2.y + pC1));
        if (CHECK) { pc0 *= m0; pc1 *= m1; }
        denC += pc0 + pc1;
        numC = fmaf(pc0, v2.x, numC);
        numC = fmaf(pc1, v2.y, numC);
        // t=32: C single w=63 (lane0) at r = il + 65
        const int r2 = rbase + 64;
        const float kx = Kc[r2], vx = Vc[r2];
        float p = ex2f(qC * (kx + px63));
        if (CHECK) p *= inbf(j0 + r2);
        denC += p; numC = fmaf(p, vx, numC);
    }

    const float sA = rcpf(1.0f + ex2f(-qA));        // sigmoid(Q)
    const float sC = rcpf(1.0f + ex2f(-qC));
    out[gq0 + A * EE] = sA * sA * numA * rcpf(denA);
    out[gq0 + C * EE] = sC * sC * numC * rcpf(denC);
}

__global__ __launch_bounds__(256, 3) void aft_local(
    const float* __restrict__ pos_bias,   // [65][256]
    float* __restrict__ out)              // [B][L][E]
{
    extern __shared__ float smem[];
    float* Kt = smem;                     // [32 ch][PITCH2 rows]
    float* Vt = smem + 32 * PITCH2;
    ull*   Pp = (ull*)(smem + 64 * PITCH2);  // [32 ch][PPITCH pairs]

    const int tid = threadIdx.x;
    const int c   = tid & 31;             // channel within block (lane)
    const int g   = tid >> 5;             // 0..7: 8-row group
    const int e0  = blockIdx.x * 32;
    const int i0  = blockIdx.y * 64;
    const int bi  = blockIdx.z;
    const int e   = e0 + c;
    const int j0  = i0 - 32;

    // Fill transposed K/V tiles: rows r=0..127 (j = j0+r), zero-fill OOB.
    for (int idx = tid; idx < 128 * 8; idx += 256) {
        const int r  = idx >> 3;
        const int cc = (idx & 7) << 2;
        const int j  = j0 + r;
        float4 kv = make_float4(0.f, 0.f, 0.f, 0.f);
        float4 vv = make_float4(0.f, 0.f, 0.f, 0.f);
        if ((unsigned)j < (unsigned)LL) {
            const int off = (bi * LL + j) * EE + e0 + cc;
            kv = *(const float4*)&g_K[off];
            vv = *(const float4*)&g_V[off];
        }
        Kt[(cc + 0) * PITCH2 + r] = kv.x;  Kt[(cc + 1) * PITCH2 + r] = kv.y;
        Kt[(cc + 2) * PITCH2 + r] = kv.z;  Kt[(cc + 3) * PITCH2 + r] = kv.w;
        Vt[(cc + 0) * PITCH2 + r] = vv.x;  Vt[(cc + 1) * PITCH2 + r] = vv.y;
        Vt[(cc + 2) * PITCH2 + r] = vv.z;  Vt[(cc + 3) * PITCH2 + r] = vv.w;
    }

    // Fill pos_bias PAIR table: Pp[c][w] = {pb[w], pb[w+1]}, w = 0..64.
    for (int idx = tid; idx < PPITCH * 32; idx += 256) {
        const int w  = idx >> 5;
        const int ci = idx & 31;
        const float lo = pos_bias[w * EE + e0 + ci];
        const float hi = (w < 64) ? pos_bias[(w + 1) * EE + e0 + ci] : 0.0f;
        float2 pr = make_float2(lo, hi);
        Pp[ci * PPITCH + w] = *(const ull*)&pr;
    }
    __syncthreads();

    const float* Kc = &Kt[c * PITCH2];
    const float* Vc = &Vt[c * PITCH2];
    const ull*   Pc = &Pp[c * PPITCH];
    const int   gq0 = (bi * LL + i0) * EE + e;

    const bool interior = (i0 >= 32) && (i0 + 96 <= LL);
    if (interior) {
        #pragma unroll 1
        for (int h = 0; h < 2; ++h) {
            const int ib = 8 * g + 4 * h;
            pair2h<0, false>(ib,     j0, gq0, Kc, Vc, Pc, out);
            pair2h<1, false>(ib + 1, j0, gq0, Kc, Vc, Pc, out);
        }
    } else {
        #pragma unroll 1
        for (int h = 0; h < 2; ++h) {
            const int ib = 8 * g + 4 * h;
            pair2h<0, true>(ib,     j0, gq0, Kc, Vc, Pc, out);
            pair2h<1, true>(ib + 1, j0, gq0, Kc, Vc, Pc, out);
        }
    }
}

// ---------------------------------------------------------------------------
// launch
// ---------------------------------------------------------------------------
extern "C" void kernel_launch(void* const* d_in, const int* in_sizes, int n_in,
                              void* d_out, int out_size)
{
    const float* q  = (const float*)d_in[0];
    const float* Wq = (const float*)d_in[1];
    const float* bq = (const float*)d_in[2];
    const float* Wk = (const float*)d_in[3];
    const float* bk = (const float*)d_in[4];
    const float* Wv = (const float*)d_in[5];
    const float* bv = (const float*)d_in[6];
    const float* pb = (const float*)d_in[7];
    float* out = (float*)d_out;

    (void)in_sizes; (void)n_in; (void)out_size;

    // smem: K/V tiles (33280 B) + pos_bias pair table (16640 B) = 49920 B
    const int aft_smem = 64 * PITCH2 * 4 + 32 * PPITCH * 8;
    static bool s_init = false;
    if (!s_init) {
        cudaFuncSetAttribute(aft_local, cudaFuncAttributeMaxDynamicSharedMemorySize,
                             aft_smem);
        s_init = true;
    }

    // 1: QKV projection on tensor cores (fp32->bf16 hi/lo split fused in-load)
    dim3 gg(32, 4, 3);
    qkv_mma<<<gg, 256>>>(q, Wq, Wk, Wv, bq, bk, bv);

    // 2: AFT local attention (hybrid MUFU/FMA exp)
    dim3 ga(EE / 32, LL / 64, BB);
    aft_local<<<ga, 256, aft_smem>>>(pb, out);
}

// round 16
// speedup vs baseline: 1.0899x; 1.0899x over previous
#include <cuda_runtime.h>
#include <cuda_fp16.h>

// Problem constants: B=4, L=1024, E=256, S=32, W=2S+1=65
#define BB 4
#define LL 1024
#define EE 256
#define LOG2E 1.4426950408889634f
#define PITCH2 130   // K/V transposed pitch (floats)
#define PBPITCH 67   // pos_bias smem pitch (3c mod 32 bijective -> conflict-free)

typedef unsigned long long ull;

// Device-global scratch (no allocations allowed)
__device__ float g_Q[BB * LL * EE];
__device__ float g_K[BB * LL * EE];
__device__ float g_V[BB * LL * EE];

// ---------------------------------------------------------------------------
// helpers
// ---------------------------------------------------------------------------
__device__ __forceinline__ float ex2f(float x) {
    float r; asm("ex2.approx.f32 %0, %1;" : "=f"(r) : "f"(x)); return r;
}
__device__ __forceinline__ float rcpf(float x) {
    float r; asm("rcp.approx.f32 %0, %1;" : "=f"(r) : "f"(x)); return r;
}
__device__ __forceinline__ float inbf(int j) {
    return ((unsigned)j < (unsigned)LL) ? 1.0f : 0.0f;
}
__device__ __forceinline__ void ldsm4(unsigned* r, unsigned addr) {
    asm volatile("ldmatrix.sync.aligned.m8n8.x4.shared.b16 {%0,%1,%2,%3}, [%4];"
                 : "=r"(r[0]), "=r"(r[1]), "=r"(r[2]), "=r"(r[3]) : "r"(addr));
}
// fp16 MMA, fp32 accumulate
__device__ __forceinline__ void mmah(float* c, const unsigned* a, const unsigned* b) {
    asm volatile(
        "mma.sync.aligned.m16n8k16.row.col.f32.f16.f16.f32 "
        "{%0,%1,%2,%3},{%4,%5,%6,%7},{%8,%9},{%0,%1,%2,%3};"
        : "+f"(c[0]), "+f"(c[1]), "+f"(c[2]), "+f"(c[3])
        : "r"(a[0]), "r"(a[1]), "r"(a[2]), "r"(a[3]), "r"(b[0]), "r"(b[1]));
}
// fp32x4 -> 4 fp16 (8B)
__device__ __forceinline__ ull cvtA4(float4 v) {
    __half h[4] = {__float2half_rn(v.x), __float2half_rn(v.y),
                   __float2half_rn(v.z), __float2half_rn(v.w)};
    return *(ull*)h;
}
// fp32x4 -> fp16 hi (8B) + fp16 residual lo (8B)
__device__ __forceinline__ void cvtW4(float4 v, ull& h, ull& l) {
    float s[4] = {v.x, v.y, v.z, v.w};
    __half hh[4], ll[4];
    #pragma unroll
    for (int j = 0; j < 4; ++j) {
        hh[j] = __float2half_rn(s[j]);
        ll[j] = __float2half_rn(s[j] - __half2float(hh[j]));
    }
    h = *(ull*)hh; l = *(ull*)ll;
}

// ---------------------------------------------------------------------------
// Kernel 1: QKV projection, fp16 2-term split on mma.sync.
// out[m][n] = sum_k A[m][k]*W[n][k] + bias[n]
// D = ah @ (wh + wl): A as single fp16 (error 2^-12 rel), W split hi/lo
// (error 2^-22). 16 HMMA per warp per ks (was 24 with bf16 3-term).
// Block 256 thr (8 warps 4x2), BM=128, BN=64, BK=32, smem pitch 40 halves.
// Prefetch of kt+1 overlaps compute of kt. grid = (32, 4, 3).
// ---------------------------------------------------------------------------
__global__ __launch_bounds__(256, 2) void qkv_mma(
    const float* __restrict__ A,
    const float* __restrict__ W0, const float* __restrict__ W1,
    const float* __restrict__ W2,
    const float* __restrict__ bq, const float* __restrict__ bk,
    const float* __restrict__ bv)
{
    __shared__ __align__(16) __half sA[128 * 40];     // A fp16
    __shared__ __align__(16) __half sW[2][64 * 40];   // W hi / lo

    const int tid = threadIdx.x;
    const int z  = blockIdx.z;
    const int m0 = blockIdx.x * 128;
    const int n0 = blockIdx.y * 64;
    const float* Wm = (z == 0) ? W0 : (z == 1) ? W1 : W2;

    const int lane = tid & 31, wid = tid >> 5;
    const int wm = wid & 3;            // warp row block (32 rows)
    const int wn = wid >> 2;           // warp col block (32 cols)

    // load mapping: A tile 128x8 float4 -> 4/thread; W tile 64x8 -> 2/thread
    const int lrow = tid >> 3;          // used with i-offsets below
    const int lc4  = tid & 7;

    float acc[2][4][4];
    #pragma unroll
    for (int mt = 0; mt < 2; ++mt)
        #pragma unroll
        for (int nt = 0; nt < 4; ++nt)
            #pragma unroll
            for (int r = 0; r < 4; ++r) acc[mt][nt][r] = 0.0f;

    // ldmatrix lane addressing
    const int mat = lane >> 3;
    const int a_m = (mat & 1) * 8 + (lane & 7);
    const int a_k = (mat >> 1) * 8;
    const int w_n = (mat >> 1) * 8 + (lane & 7);
    const int w_k = (mat & 1) * 8;

    float4 pa[4], pw[2];
    {
        #pragma unroll
        for (int i = 0; i < 4; ++i)
            pa[i] = *(const float4*)&A[(m0 + lrow + i * 32) * EE + lc4 * 4];
        #pragma unroll
        for (int i = 0; i < 2; ++i)
            pw[i] = *(const float4*)&Wm[(n0 + lrow + i * 32) * EE + lc4 * 4];
    }

    for (int kt = 0; kt < 8; ++kt) {
        __syncthreads();   // previous tile fully consumed
        #pragma unroll
        for (int i = 0; i < 4; ++i)
            *(ull*)&sA[(lrow + i * 32) * 40 + lc4 * 4] = cvtA4(pa[i]);
        #pragma unroll
        for (int i = 0; i < 2; ++i) {
            ull h, l; cvtW4(pw[i], h, l);
            *(ull*)&sW[0][(lrow + i * 32) * 40 + lc4 * 4] = h;
            *(ull*)&sW[1][(lrow + i * 32) * 40 + lc4 * 4] = l;
        }
        __syncthreads();

        if (kt < 7) {   // prefetch next k-tile before compute
            const int k0 = (kt + 1) * 32;
            #pragma unroll
            for (int i = 0; i < 4; ++i)
                pa[i] = *(const float4*)&A[(m0 + lrow + i * 32) * EE + k0 + lc4 * 4];
            #pragma unroll
            for (int i = 0; i < 2; ++i)
                pw[i] = *(const float4*)&Wm[(n0 + lrow + i * 32) * EE + k0 + lc4 * 4];
        }

        #pragma unroll
        for (int ks = 0; ks < 2; ++ks) {
            unsigned ah[2][4], bh[4][2], bl[4][2];
            #pragma unroll
            for (int mt = 0; mt < 2; ++mt) {
                unsigned adr = (unsigned)__cvta_generic_to_shared(
                    &sA[(wm * 32 + mt * 16 + a_m) * 40 + ks * 16 + a_k]);
                ldsm4(ah[mt], adr);
            }
            #pragma unroll
            for (int np = 0; np < 2; ++np) {
                unsigned t[4];
                unsigned adr_h = (unsigned)__cvta_generic_to_shared(
                    &sW[0][(wn * 32 + np * 16 + w_n) * 40 + ks * 16 + w_k]);
                ldsm4(t, adr_h);
                bh[np * 2][0] = t[0]; bh[np * 2][1] = t[1];
                bh[np * 2 + 1][0] = t[2]; bh[np * 2 + 1][1] = t[3];
                unsigned adr_l = (unsigned)__cvta_generic_to_shared(
                    &sW[1][(wn * 32 + np * 16 + w_n) * 40 + ks * 16 + w_k]);
                ldsm4(t, adr_l);
                bl[np * 2][0] = t[0]; bl[np * 2][1] = t[1];
                bl[np * 2 + 1][0] = t[2]; bl[np * 2 + 1][1] = t[3];
            }
            #pragma unroll
            for (int mt = 0; mt < 2; ++mt)
                #pragma unroll
                for (int nt = 0; nt < 4; ++nt) {
                    mmah(acc[mt][nt], ah[mt], bh[nt]);   // ah * wh
                    mmah(acc[mt][nt], ah[mt], bl[nt]);   // ah * wl
                }
        }
    }

    float* out = (z == 0) ? g_Q : (z == 1) ? g_K : g_V;
    const float* bias = (z == 0) ? bq : (z == 1) ? bk : bv;
    #pragma unroll
    for (int nt = 0; nt < 4; ++nt) {
        const int n = n0 + wn * 32 + nt * 8 + (lane & 3) * 2;
        const float b0 = bias[n], b1 = bias[n + 1];
        #pragma unroll
        for (int mt = 0; mt < 2; ++mt) {
            const int m = m0 + wm * 32 + mt * 16 + (lane >> 2);
            float2 r0 = make_float2(acc[mt][nt][0] + b0, acc[mt][nt][1] + b1);
            float2 r1 = make_float2(acc[mt][nt][2] + b0, acc[mt][nt][3] + b1);
            *(float2*)&out[m * EE + n] = r0;
            *(float2*)&out[(m + 8) * EE + n] = r1;
        }
    }
}

// ---------------------------------------------------------------------------
// Kernel 2: AFT-local attention — verified round-12 version (33.5us ncu).
// 2-row pairing (il, il+2); pos_bias scalar table in smem (pitch 67);
// 64 rows x 32 ch tile; __launch_bounds__(256,4). Unshifted softmax.
// ---------------------------------------------------------------------------
template <int PAR, bool CHECK>
__device__ __forceinline__ void pair2s(
    const int il, const int j0, const int gq0,
    const float* __restrict__ Kc, const float* __restrict__ Vc,
    const float* __restrict__ pbc, const float px1, const float px63,
    float* __restrict__ out)
{
    const int A = il, C = il + 2;
    const float qA = g_Q[gq0 + A * EE] * LOG2E;
    const float qC = g_Q[gq0 + C * EE] * LOG2E;

    float denA, numA, denC, numC;
    {
        float vA0 = 1.f, vA6 = 1.f, vC0 = 1.f, vC6 = 1.f;
        if (CHECK) {
            vA0 = inbf(j0 + A); vA6 = inbf(j0 + A + 64);
            vC0 = inbf(j0 + C); vC6 = inbf(j0 + C + 64);
        }
        denA = vA0 + vA6;  numA = Vc[A] + Vc[A + 64];
        denC = vC0 + vC6;  numC = Vc[C] + Vc[C + 64];
    }

    if (PAR == 0) {
        float p = ex2f(qA * (Kc[il + 1] + px1));
        if (CHECK) p *= inbf(j0 + il + 1);
        denA += p; numA = fmaf(p, Vc[il + 1], numA);
    }

    const int rbase = il + 2 - PAR;
    float pA0 = pbc[2 - PAR], pA1 = pbc[3 - PAR];
    float pC0, pC1;

    {
        const float2 k2 = *(const float2*)&Kc[rbase];
        const float2 v2 = *(const float2*)&Vc[rbase];
        float m0 = 1.f, m1 = 1.f;
        if (CHECK) { m0 = inbf(j0 + rbase); m1 = inbf(j0 + rbase + 1); }
        float p0 = ex2f(qA * (k2.x + pA0));
        float p1 = ex2f(qA * (k2.y + pA1));
        if (CHECK) { p0 *= m0; p1 *= m1; }
        denA += p0 + p1;
        numA = fmaf(p0, v2.x, numA);
        numA = fmaf(p1, v2.y, numA);
        if (PAR == 0) {
            float p = ex2f(qC * (k2.y + px1));
            if (CHECK) p *= m1;
            denC += p; numC = fmaf(p, v2.y, numC);
        }
        pC0 = pA0; pC1 = pA1;
        pA0 = pbc[4 - PAR]; pA1 = pbc[5 - PAR];
    }

    #pragma unroll 6
    for (int t = 1; t <= 30; ++t) {
        const int r = rbase + 2 * t;
        const float2 k2 = *(const float2*)&Kc[r];
        const float2 v2 = *(const float2*)&Vc[r];
        float m0 = 1.f, m1 = 1.f;
        if (CHECK) { m0 = inbf(j0 + r); m1 = inbf(j0 + r + 1); }
        float pa0 = ex2f(qA * (k2.x + pA0));
        float pa1 = ex2f(qA * (k2.y + pA1));
        float pc0 = ex2f(qC * (k2.x + pC0));
        float pc1 = ex2f(qC * (k2.y + pC1));
        if (CHECK) { pa0 *= m0; pa1 *= m1; pc0 *= m0; pc1 *= m1; }
        denA += pa0 + pa1;
        denC += pc0 + pc1;
        numA = fmaf(pa0, v2.x, numA);  numA = fmaf(pa1, v2.y, numA);
        numC = fmaf(pc0, v2.x, numC);  numC = fmaf(pc1, v2.y, numC);
        pC0 = pA0; pC1 = pA1;
        const int wN = 2 - PAR + 2 * t + 2;
        pA0 = pbc[wN]; pA1 = pbc[wN + 1];
    }

    if (PAR == 0) {
        const int r = rbase + 62;
        const float2 k2 = *(const float2*)&Kc[r];
        const float2 v2 = *(const float2*)&Vc[r];
        float m0 = 1.f, m1 = 1.f;
        if (CHECK) { m0 = inbf(j0 + r); m1 = inbf(j0 + r + 1); }
        float pc0 = ex2f(qC * (k2.x + pC0));
        float pc1 = ex2f(qC * (k2.y + pC1));
        if (CHECK) { pc0 *= m0; pc1 *= m1; }
        denC += pc0 + pc1;
        numC = fmaf(pc0, v2.x, numC);
        numC = fmaf(pc1, v2.y, numC);
    } else {
        const int r = rbase + 62;
        const float2 k2 = *(const float2*)&Kc[r];
        const float2 v2 = *(const float2*)&Vc[r];
        float m0 = 1.f, m1 = 1.f;
        if (CHECK) { m0 = inbf(j0 + r); m1 = inbf(j0 + r + 1); }
        float pa = ex2f(qA * (k2.x + px63));
        if (CHECK) pa *= m0;
        denA += pa; numA = fmaf(pa, v2.x, numA);
        float pc0 = ex2f(qC * (k2.x + pC0));
        float pc1 = ex2f(qC * (k2.y + pC1));
        if (CHECK) { pc0 *= m0; pc1 *= m1; }
        denC += pc0 + pc1;
        numC = fmaf(pc0, v2.x, numC);
        numC = fmaf(pc1, v2.y, numC);
        const int r2 = rbase + 64;
        const float kx = Kc[r2], vx = Vc[r2];
        float p = ex2f(qC * (kx + px63));
        if (CHECK) p *= inbf(j0 + r2);
        denC += p; numC = fmaf(p, vx, numC);
    }

    const float sA = rcpf(1.0f + ex2f(-qA));
    const float sC = rcpf(1.0f + ex2f(-qC));
    out[gq0 + A * EE] = sA * sA * numA * rcpf(denA);
    out[gq0 + C * EE] = sC * sC * numC * rcpf(denC);
}

__global__ __launch_bounds__(256, 4) void aft_local(
    const float* __restrict__ pos_bias,   // [65][256]
    float* __restrict__ out)              // [B][L][E]
{
    extern __shared__ float fsm[];
    float* Kt = fsm;                      // [32 ch][PITCH2 rows]
    float* Vt = fsm + 32 * PITCH2;
    float* Pb = fsm + 64 * PITCH2;        // [32 ch][PBPITCH]

    const int tid = threadIdx.x;
    const int c   = tid & 31;
    const int g   = tid >> 5;
    const int e0  = blockIdx.x * 32;
    const int i0  = blockIdx.y * 64;
    const int bi  = blockIdx.z;
    const int e   = e0 + c;
    const int j0  = i0 - 32;

    for (int idx = tid; idx < 128 * 8; idx += 256) {
        const int r  = idx >> 3;
        const int cc = (idx & 7) << 2;
        const int j  = j0 + r;
        float4 kv = make_float4(0.f, 0.f, 0.f, 0.f);
        float4 vv = make_float4(0.f, 0.f, 0.f, 0.f);
        if ((unsigned)j < (unsigned)LL) {
            const int off = (bi * LL + j) * EE + e0 + cc;
            kv = *(const float4*)&g_K[off];
            vv = *(const float4*)&g_V[off];
        }
        Kt[(cc + 0) * PITCH2 + r] = kv.x;  Kt[(cc + 1) * PITCH2 + r] = kv.y;
        Kt[(cc + 2) * PITCH2 + r] = kv.z;  Kt[(cc + 3) * PITCH2 + r] = kv.w;
        Vt[(cc + 0) * PITCH2 + r] = vv.x;  Vt[(cc + 1) * PITCH2 + r] = vv.y;
        Vt[(cc + 2) * PITCH2 + r] = vv.z;  Vt[(cc + 3) * PITCH2 + r] = vv.w;
    }

    for (int idx = tid; idx < 65 * 32; idx += 256) {
        const int w  = idx >> 5;
        const int ci = idx & 31;
        Pb[ci * PBPITCH + w] = pos_bias[w * EE + e0 + ci];
    }
    __syncthreads();

    const float* Kc  = &Kt[c * PITCH2];
    const float* Vc  = &Vt[c * PITCH2];
    const float* pbc = &Pb[c * PBPITCH];
    const float px1  = pbc[1], px63 = pbc[63];
    const int   gq0  = (bi * LL + i0) * EE + e;

    const bool interior = (i0 >= 32) && (i0 + 96 <= LL);
    if (interior) {
        #pragma unroll 1
        for (int h = 0; h < 2; ++h) {
            const int ib = 8 * g + 4 * h;
            pair2s<0, false>(ib,     j0, gq0, Kc, Vc, pbc, px1, px63, out);
            pair2s<1, false>(ib + 1, j0, gq0, Kc, Vc, pbc, px1, px63, out);
        }
    } else {
        #pragma unroll 1
        for (int h = 0; h < 2; ++h) {
            const int ib = 8 * g + 4 * h;
            pair2s<0, true>(ib,     j0, gq0, Kc, Vc, pbc, px1, px63, out);
            pair2s<1, true>(ib + 1, j0, gq0, Kc, Vc, pbc, px1, px63, out);
        }
    }
}

// ---------------------------------------------------------------------------
// launch
// ---------------------------------------------------------------------------
extern "C" void kernel_launch(void* const* d_in, const int* in_sizes, int n_in,
                              void* d_out, int out_size)
{
    const float* q  = (const float*)d_in[0];
    const float* Wq = (const float*)d_in[1];
    const float* bq = (const float*)d_in[2];
    const float* Wk = (const float*)d_in[3];
    const float* bk = (const float*)d_in[4];
    const float* Wv = (const float*)d_in[5];
    const float* bv = (const float*)d_in[6];
    const float* pb = (const float*)d_in[7];
    float* out = (float*)d_out;

    (void)in_sizes; (void)n_in; (void)out_size;

    // 1: QKV projection — fp16 2-term split on mma.sync
    dim3 gg(32, 4, 3);
    qkv_mma<<<gg, 256>>>(q, Wq, Wk, Wv, bq, bk, bv);

    // 2: AFT local attention (round-12 verified; 41856B smem < 48KB default)
    const int aft_smem = (64 * PITCH2 + 32 * PBPITCH) * 4;
    dim3 ga(EE / 32, LL / 64, BB);
    aft_local<<<ga, 256, aft_smem>>>(pb, out);
}